// round 12
// baseline (speedup 1.0000x reference)
#include <cuda_runtime.h>
#include <cstdint>

#define WARPS_PER_BLOCK 8     // 256-thread blocks: validated optimum (R7/R8/R11 sweep)
#define TOK_PER_WARP    2
#define CHUNKS          128   // dim 512 / 4 int4 chunks per row (2KB row)

// 16B non-coherent load with 256B L2 fetch granularity: each L2 miss pulls
// 256B instead of a 128B sector -> larger DRAM bursts on the random row
// gather (we consume the whole 2KB row, so nothing is wasted).
__device__ __forceinline__ int4 ldg_nc_256(const int4* p) {
    int4 v;
    asm volatile("ld.global.nc.L2::256B.v4.b32 {%0,%1,%2,%3}, [%4];"
                 : "=r"(v.x), "=r"(v.y), "=r"(v.z), "=r"(v.w)
                 : "l"(p));
    return v;
}

// Write-through 16B store: output is write-once-never-read; .wt avoids holding
// L2 allocation priority so the write stream doesn't churn tags against the
// concurrent gather reads (the cross-replay overlap phase that sets wall time).
__device__ __forceinline__ void stg_wt(float4* p, float4 v) {
    asm volatile("st.global.wt.v4.f32 [%0], {%1,%2,%3,%4};"
                 :: "l"(p), "f"(v.x), "f"(v.y), "f"(v.z), "f"(v.w) : "memory");
}

__device__ __forceinline__ void dq_store(float4* o, int lane,
                                         int4 a0, int4 a1, int4 a2, int4 a3,
                                         float s) {
    stg_wt(&o[lane],      make_float4((float)a0.x * s, (float)a0.y * s,
                                      (float)a0.z * s, (float)a0.w * s));
    stg_wt(&o[lane + 32], make_float4((float)a1.x * s, (float)a1.y * s,
                                      (float)a1.z * s, (float)a1.w * s));
    stg_wt(&o[lane + 64], make_float4((float)a2.x * s, (float)a2.y * s,
                                      (float)a2.z * s, (float)a2.w * s));
    stg_wt(&o[lane + 96], make_float4((float)a3.x * s, (float)a3.y * s,
                                      (float)a3.z * s, (float)a3.w * s));
}

// One warp per 2 tokens; all 8 row loads + 2 scale loads in flight before any
// consume. EXACT=1: n_tokens is a multiple of tokens-per-block -> no bounds
// predicates at all. Dtype (int64 vs int32) detected inline via ballot over
// odd 32-bit words (little-endian non-negative int64 => all zero).
template <bool EXACT>
__global__ __launch_bounds__(WARPS_PER_BLOCK * 32)
void quant_embed_mlp_kernel(const unsigned int* __restrict__ x_raw,
                            const int4* __restrict__ w4,
                            const float* __restrict__ scales,
                            float4* __restrict__ out4,
                            int n_tokens)
{
    const int warp_id = threadIdx.x >> 5;
    const int lane    = threadIdx.x & 31;

    // ---- inline dtype detection (uniform result across grid) ----
    unsigned probe = 0u;
    {
        int wmax = n_tokens * 2;          // words available if int64
        int widx = 2 * lane + 1;
        if (widx < wmax) probe = x_raw[widx];
    }
    const bool is64 = (__ballot_sync(0xFFFFFFFFu, probe != 0u) == 0u);

    const int base_token = (blockIdx.x * WARPS_PER_BLOCK + warp_id) * TOK_PER_WARP;
    if (!EXACT && base_token >= n_tokens) return;
    const bool has1 = EXACT || (base_token + 1) < n_tokens;

    // ---- indices + scales (lane 0/1 load, broadcast) ----
    long long myidx = 0;
    float mys = 0.0f;
    if (lane < TOK_PER_WARP && (EXACT || base_token + lane < n_tokens)) {
        myidx = is64 ? ((const long long*)x_raw)[base_token + lane]
                     : (long long)((const int*)x_raw)[base_token + lane];
        mys = __ldg(&scales[myidx]);
    }
    const long long idx0 = __shfl_sync(0xFFFFFFFFu, myidx, 0);
    const long long idx1 = __shfl_sync(0xFFFFFFFFu, myidx, 1);

    const int4* r0 = w4 + idx0 * CHUNKS;
    const int4* r1 = w4 + idx1 * CHUNKS;

    // ---- issue ALL row loads back-to-back ----
    int4 a0 = ldg_nc_256(&r0[lane]);
    int4 a1 = ldg_nc_256(&r0[lane + 32]);
    int4 a2 = ldg_nc_256(&r0[lane + 64]);
    int4 a3 = ldg_nc_256(&r0[lane + 96]);
    int4 b0, b1, b2, b3;
    if (has1) {
        b0 = ldg_nc_256(&r1[lane]);
        b1 = ldg_nc_256(&r1[lane + 32]);
        b2 = ldg_nc_256(&r1[lane + 64]);
        b3 = ldg_nc_256(&r1[lane + 96]);
    }
    const float s0 = __shfl_sync(0xFFFFFFFFu, mys, 0);
    const float s1 = __shfl_sync(0xFFFFFFFFu, mys, 1);

    // ---- dequant + write-through stores ----
    dq_store(out4 + (long long)base_token * CHUNKS, lane, a0, a1, a2, a3, s0);
    if (has1)
        dq_store(out4 + (long long)(base_token + 1) * CHUNKS, lane,
                 b0, b1, b2, b3, s1);
}

// Generic fallback for dims other than 512.
__global__ __launch_bounds__(256)
void quant_embed_generic_kernel(const unsigned int* __restrict__ x_raw,
                                const int4* __restrict__ w4,
                                const float* __restrict__ scales,
                                float4* __restrict__ out4,
                                int chunks_per_row, int n_tokens)
{
    const int lane = threadIdx.x & 31;
    unsigned probe = 0u;
    {
        int wmax = n_tokens * 2;
        int widx = 2 * lane + 1;
        if (widx < wmax) probe = x_raw[widx];
    }
    const bool is64 = (__ballot_sync(0xFFFFFFFFu, probe != 0u) == 0u);

    const int warps_per_block = blockDim.x >> 5;
    const int token = blockIdx.x * warps_per_block + (threadIdx.x >> 5);
    if (token >= n_tokens) return;
    long long idx = is64 ? ((const long long*)x_raw)[token]
                         : (long long)((const int*)x_raw)[token];
    float s = __ldg(&scales[idx]);
    const int4* wrow = w4 + idx * chunks_per_row;
    float4* orow = out4 + (long long)token * chunks_per_row;
    for (int c = lane; c < chunks_per_row; c += 32) {
        int4 w = __ldg(&wrow[c]);
        __stcs(&orow[c], make_float4((float)w.x * s, (float)w.y * s,
                                     (float)w.z * s, (float)w.w * s));
    }
}

extern "C" void kernel_launch(void* const* d_in, const int* in_sizes, int n_in,
                              void* d_out, int out_size) {
    const unsigned int* x      = (const unsigned int*)d_in[0];
    const int4*         w4     = (const int4*)d_in[1];
    const float*        scales = (const float*)d_in[2];
    float4*             out4   = (float4*)d_out;

    const int n_tokens = in_sizes[0];
    const int dim      = out_size / n_tokens;   // 512
    const int chunks   = dim / 4;               // 128

    if (chunks == CHUNKS) {
        const int tokens_per_block = WARPS_PER_BLOCK * TOK_PER_WARP;  // 16
        const int blocks = (n_tokens + tokens_per_block - 1) / tokens_per_block;
        if (n_tokens % tokens_per_block == 0) {
            quant_embed_mlp_kernel<true><<<blocks, WARPS_PER_BLOCK * 32>>>(
                x, w4, scales, out4, n_tokens);
        } else {
            quant_embed_mlp_kernel<false><<<blocks, WARPS_PER_BLOCK * 32>>>(
                x, w4, scales, out4, n_tokens);
        }
    } else {
        const int threads = 256;
        const int wpb = threads / 32;
        const int blocks = (n_tokens + wpb - 1) / wpb;
        quant_embed_generic_kernel<<<blocks, threads>>>(x, w4, scales, out4,
                                                        chunks, n_tokens);
    }
}

// round 13
// speedup vs baseline: 1.1458x; 1.1458x over previous
#include <cuda_runtime.h>
#include <cstdint>

#define WARPS_PER_BLOCK 8     // 256-thread blocks: validated optimum (R7/R8/R11 sweep)
#define TOK_PER_WARP    2
#define CHUNKS          128   // dim 512 / 4 int4 chunks per row (2KB row)

// 16B non-coherent load with 256B L2 fetch granularity: each L2 miss pulls
// 256B instead of a 128B sector -> larger DRAM bursts on the random row
// gather (we consume the whole 2KB row, so nothing is wasted).
__device__ __forceinline__ int4 ldg_nc_256(const int4* p) {
    int4 v;
    asm volatile("ld.global.nc.L2::256B.v4.b32 {%0,%1,%2,%3}, [%4];"
                 : "=r"(v.x), "=r"(v.y), "=r"(v.z), "=r"(v.w)
                 : "l"(p));
    return v;
}

// Evict-first (.cs) write-back stores: dirty output lines drain from L2 to
// DRAM lazily, overlapping the NEXT graph replay's latency-bound prologue
// (validated: .wt eager writeback regressed wall time by 1.6us).
__device__ __forceinline__ void dq_store(float4* o, int lane,
                                         int4 a0, int4 a1, int4 a2, int4 a3,
                                         float s) {
    __stcs(&o[lane],      make_float4((float)a0.x * s, (float)a0.y * s,
                                      (float)a0.z * s, (float)a0.w * s));
    __stcs(&o[lane + 32], make_float4((float)a1.x * s, (float)a1.y * s,
                                      (float)a1.z * s, (float)a1.w * s));
    __stcs(&o[lane + 64], make_float4((float)a2.x * s, (float)a2.y * s,
                                      (float)a2.z * s, (float)a2.w * s));
    __stcs(&o[lane + 96], make_float4((float)a3.x * s, (float)a3.y * s,
                                      (float)a3.z * s, (float)a3.w * s));
}

// One warp per 2 tokens; all 8 row loads + 2 scale loads in flight before any
// consume. EXACT=1: n_tokens is a multiple of tokens-per-block -> no bounds
// predicates at all. Dtype (int64 vs int32) detected inline via ballot over
// odd 32-bit words (little-endian non-negative int64 => all zero).
template <bool EXACT>
__global__ __launch_bounds__(WARPS_PER_BLOCK * 32)
void quant_embed_mlp_kernel(const unsigned int* __restrict__ x_raw,
                            const int4* __restrict__ w4,
                            const float* __restrict__ scales,
                            float4* __restrict__ out4,
                            int n_tokens)
{
    const int warp_id = threadIdx.x >> 5;
    const int lane    = threadIdx.x & 31;

    // ---- inline dtype detection (uniform result across grid) ----
    unsigned probe = 0u;
    {
        int wmax = n_tokens * 2;          // words available if int64
        int widx = 2 * lane + 1;
        if (widx < wmax) probe = x_raw[widx];
    }
    const bool is64 = (__ballot_sync(0xFFFFFFFFu, probe != 0u) == 0u);

    const int base_token = (blockIdx.x * WARPS_PER_BLOCK + warp_id) * TOK_PER_WARP;
    if (!EXACT && base_token >= n_tokens) return;
    const bool has1 = EXACT || (base_token + 1) < n_tokens;

    // ---- indices + scales (lane 0/1 load, broadcast) ----
    long long myidx = 0;
    float mys = 0.0f;
    if (lane < TOK_PER_WARP && (EXACT || base_token + lane < n_tokens)) {
        myidx = is64 ? ((const long long*)x_raw)[base_token + lane]
                     : (long long)((const int*)x_raw)[base_token + lane];
        mys = __ldg(&scales[myidx]);
    }
    const long long idx0 = __shfl_sync(0xFFFFFFFFu, myidx, 0);
    const long long idx1 = __shfl_sync(0xFFFFFFFFu, myidx, 1);

    const int4* r0 = w4 + idx0 * CHUNKS;
    const int4* r1 = w4 + idx1 * CHUNKS;

    // ---- issue ALL row loads back-to-back ----
    int4 a0 = ldg_nc_256(&r0[lane]);
    int4 a1 = ldg_nc_256(&r0[lane + 32]);
    int4 a2 = ldg_nc_256(&r0[lane + 64]);
    int4 a3 = ldg_nc_256(&r0[lane + 96]);
    int4 b0, b1, b2, b3;
    if (has1) {
        b0 = ldg_nc_256(&r1[lane]);
        b1 = ldg_nc_256(&r1[lane + 32]);
        b2 = ldg_nc_256(&r1[lane + 64]);
        b3 = ldg_nc_256(&r1[lane + 96]);
    }
    const float s0 = __shfl_sync(0xFFFFFFFFu, mys, 0);
    const float s1 = __shfl_sync(0xFFFFFFFFu, mys, 1);

    // ---- dequant + streaming stores (don't pollute L2 with output) ----
    dq_store(out4 + (long long)base_token * CHUNKS, lane, a0, a1, a2, a3, s0);
    if (has1)
        dq_store(out4 + (long long)(base_token + 1) * CHUNKS, lane,
                 b0, b1, b2, b3, s1);
}

// Generic fallback for dims other than 512.
__global__ __launch_bounds__(256)
void quant_embed_generic_kernel(const unsigned int* __restrict__ x_raw,
                                const int4* __restrict__ w4,
                                const float* __restrict__ scales,
                                float4* __restrict__ out4,
                                int chunks_per_row, int n_tokens)
{
    const int lane = threadIdx.x & 31;
    unsigned probe = 0u;
    {
        int wmax = n_tokens * 2;
        int widx = 2 * lane + 1;
        if (widx < wmax) probe = x_raw[widx];
    }
    const bool is64 = (__ballot_sync(0xFFFFFFFFu, probe != 0u) == 0u);

    const int warps_per_block = blockDim.x >> 5;
    const int token = blockIdx.x * warps_per_block + (threadIdx.x >> 5);
    if (token >= n_tokens) return;
    long long idx = is64 ? ((const long long*)x_raw)[token]
                         : (long long)((const int*)x_raw)[token];
    float s = __ldg(&scales[idx]);
    const int4* wrow = w4 + idx * chunks_per_row;
    float4* orow = out4 + (long long)token * chunks_per_row;
    for (int c = lane; c < chunks_per_row; c += 32) {
        int4 w = __ldg(&wrow[c]);
        __stcs(&orow[c], make_float4((float)w.x * s, (float)w.y * s,
                                     (float)w.z * s, (float)w.w * s));
    }
}

extern "C" void kernel_launch(void* const* d_in, const int* in_sizes, int n_in,
                              void* d_out, int out_size) {
    const unsigned int* x      = (const unsigned int*)d_in[0];
    const int4*         w4     = (const int4*)d_in[1];
    const float*        scales = (const float*)d_in[2];
    float4*             out4   = (float4*)d_out;

    const int n_tokens = in_sizes[0];
    const int dim      = out_size / n_tokens;   // 512
    const int chunks   = dim / 4;               // 128

    if (chunks == CHUNKS) {
        const int tokens_per_block = WARPS_PER_BLOCK * TOK_PER_WARP;  // 16
        const int blocks = (n_tokens + tokens_per_block - 1) / tokens_per_block;
        if (n_tokens % tokens_per_block == 0) {
            quant_embed_mlp_kernel<true><<<blocks, WARPS_PER_BLOCK * 32>>>(
                x, w4, scales, out4, n_tokens);
        } else {
            quant_embed_mlp_kernel<false><<<blocks, WARPS_PER_BLOCK * 32>>>(
                x, w4, scales, out4, n_tokens);
        }
    } else {
        const int threads = 256;
        const int wpb = threads / 32;
        const int blocks = (n_tokens + wpb - 1) / wpb;
        quant_embed_generic_kernel<<<blocks, threads>>>(x, w4, scales, out4,
                                                        chunks, n_tokens);
    }
}